// round 14
// baseline (speedup 1.0000x reference)
#include <cuda_runtime.h>
#include <cstdint>

// Problem constants
#define BB      64
#define TT      2048
#define NIN     64
#define NH      512
#define NOUT    64
#define FPIT    60
#define TOTIT   (FPIT + TT)

// Decomposition (R10 proven): 8 CTAs/cluster, 16 clusters,
// 2 streams x 2 batches per cluster, 256 threads, A in registers.
#define CSIZE   8
#define NCLUST  16
#define ROWS    64
#define THREADS 256
#define NWARP   8
#define JEXT    (NH + NIN)   // 576
#define KPT     18           // j's per lane: j = lane + 32k
#define NBUF    3            // triple buffer

typedef unsigned long long ull;

struct Smem {
    float hx[2][NBUF][JEXT][4];    // [stream][buf][j] = {b0,b0,b1,b1}
    float Wl[8][NH];               // this rank's 8 W_lin rows
    uint32_t flags[2][NBUF][8];    // [stream][buf][src_rank] = step counter
};
#define SMEM_BYTES  ((int)sizeof(Smem))
#define HXB_BYTES   (JEXT * 4 * 4)                        // 9216 per buffer
#define HX_OFF(s, b) ((uint32_t)(((s) * NBUF + (b)) * HXB_BYTES))
#define FL_OFF(s, b) ((uint32_t)(((s) * NBUF + (b)) * 32))

__device__ __forceinline__ uint32_t smem_u32(const void* p) {
    uint32_t a;
    asm("{ .reg .u64 t; cvta.to.shared.u64 t, %1; cvt.u32.u64 %0, t; }"
        : "=r"(a) : "l"(p));
    return a;
}
__device__ __forceinline__ uint32_t mapa_u32(uint32_t addr, uint32_t rank) {
    uint32_t r;
    asm("mapa.shared::cluster.u32 %0, %1, %2;" : "=r"(r) : "r"(addr), "r"(rank));
    return r;
}
__device__ __forceinline__ ull pack2(float a) {
    ull r;
    asm("mov.b64 %0, {%1, %1};" : "=l"(r) : "r"(__float_as_uint(a)));
    return r;
}
__device__ __forceinline__ ull packab(float a, float b) {
    ull r;
    asm("mov.b64 %0, {%1, %2};" : "=l"(r) : "r"(__float_as_uint(a)), "r"(__float_as_uint(b)));
    return r;
}
__device__ __forceinline__ void unpack2(ull v, float& a, float& b) {
    uint32_t x, y;
    asm("mov.b64 {%0, %1}, %2;" : "=r"(x), "=r"(y) : "l"(v));
    a = __uint_as_float(x); b = __uint_as_float(y);
}
__device__ __forceinline__ void ffma2(ull& acc, ull a, ull b) {
    asm("fma.rn.f32x2 %0, %1, %2, %0;" : "+l"(acc) : "l"(a), "l"(b));
}
__device__ __forceinline__ ull addf2(ull a, ull b) {
    ull r;
    asm("add.rn.f32x2 %0, %1, %2;" : "=l"(r) : "l"(a), "l"(b));
    return r;
}
__device__ __forceinline__ ull shfl64(ull v, int m) {
    uint32_t x, y;
    asm("mov.b64 {%0, %1}, %2;" : "=r"(x), "=r"(y) : "l"(v));
    x = __shfl_xor_sync(0xffffffffu, x, m);
    y = __shfl_xor_sync(0xffffffffu, y, m);
    ull r;
    asm("mov.b64 %0, {%1, %2};" : "=l"(r) : "r"(x), "r"(y));
    return r;
}
__device__ __forceinline__ float tanh_fast(float x) {
    float r;
    asm("tanh.approx.f32 %0, %1;" : "=f"(r) : "f"(x));
    return r;
}

// flag publish: release store orders all our CTA's prior (bar.sync-ordered)
// DSMEM data stores before the flag becomes visible at cluster scope
#define FLAG_PUB(addr, val) \
    asm volatile("st.release.cluster.shared::cluster.u32 [%0], %1;" \
                 :: "r"(addr), "r"(val) : "memory")

// poll one flag word (this CTA's SMEM, written remotely) until >= need.
__device__ __forceinline__ void flag_wait(uint32_t addr, uint32_t need) {
    uint32_t v;
    do {
        asm volatile("ld.acquire.cluster.shared::cta.u32 %0, [%1];"
                     : "=r"(v) : "r"(addr) : "memory");
    } while (__any_sync(0xffffffffu, v < need));
}

// Head for stream s (2 batches): warp w owns output column rank*8 + w.
// hx rows are {b0,b0,b1,b1}; accumulate duplicated dots per batch.
__device__ __forceinline__ void do_head(const Smem* S, const ulonglong2* hp2,
                                        int w, int lane, int pb0, int s, int rank,
                                        float blr, int tt, float* __restrict__ out)
{
    ull ax = 0ull, ay = 0ull;
    const float* wl = &S->Wl[w][0];
    #pragma unroll
    for (int k = 0; k < 16; ++k) {
        int j = k * 32 + lane;
        ull w2 = pack2(wl[j]);
        ulonglong2 hv = hp2[j];
        ffma2(ax, w2, hv.x);
        ffma2(ay, w2, hv.y);
    }
    #pragma unroll
    for (int m = 16; m >= 1; m >>= 1) {
        ax = addf2(ax, shfl64(ax, m));
        ay = addf2(ay, shfl64(ay, m));
    }
    if (lane < 2) {
        float x0, x1, y0, y1;
        unpack2(ax, x0, x1);
        unpack2(ay, y0, y1);
        float v = lane ? y0 : x0;   // both halves identical; take low
        out[(pb0 + s * 2 + lane) * (TT * NOUT) + tt * NOUT + rank * 8 + w] = v + blr;
    }
}

extern __shared__ float smem_raw[];

__global__ void __cluster_dims__(CSIZE, 1, 1) __launch_bounds__(THREADS, 1)
rnn_lyapunov_kernel(const float* __restrict__ u,
                    const float* __restrict__ W_ih,
                    const float* __restrict__ W_hh,
                    const float* __restrict__ b_ih,
                    const float* __restrict__ b_hh,
                    const float* __restrict__ omega,
                    const float* __restrict__ W_lin,
                    const float* __restrict__ b_lin,
                    float* __restrict__ out)
{
    Smem* S = reinterpret_cast<Smem*>(smem_raw);
    const int tid  = threadIdx.x;
    const int w    = tid >> 5;
    const int lane = tid & 31;

    uint32_t rank;
    asm("mov.u32 %0, %%cluster_ctarank;" : "=r"(rank));
    const int cid = blockIdx.x >> 3;
    const int r0  = (int)rank * ROWS;
    const int pb0 = cid * 4;

    // ---- A into registers, row-pair packed: Apair[p][k] = {A[2p][j], A[2p+1][j]}
    ull Apair[4][KPT];
    {
        const int rg0 = r0 + w * 8;
        #pragma unroll
        for (int p = 0; p < 4; ++p) {
            const int re = rg0 + 2 * p;
            const int ro = re + 1;
            #pragma unroll
            for (int k = 0; k < 16; ++k) {
                int j = lane + 32 * k;
                float om = omega[j];
                float om2 = om * om;
                Apair[p][k] = packab(W_hh[re * NH + j] * om2,
                                     W_hh[ro * NH + j] * om2);
            }
            Apair[p][16] = packab(W_ih[re * NIN + lane],
                                  W_ih[ro * NIN + lane]);
            Apair[p][17] = packab(W_ih[re * NIN + 32 + lane],
                                  W_ih[ro * NIN + 32 + lane]);
        }
    }

    // ---- SMEM one-time loads ----
    for (int idx = tid; idx < 8 * NH; idx += THREADS) {
        int o = idx >> 9;
        int j = idx & (NH - 1);
        S->Wl[o][j] = W_lin[((int)rank * 8 + o) * NH + j];
    }
    // hx zero; flags zero
    for (int idx = tid; idx < 2 * NBUF * JEXT * 4; idx += THREADS)
        (&S->hx[0][0][0][0])[idx] = 0.0f;
    if (tid < 2 * NBUF * 8)
        (&S->flags[0][0][0])[tid] = 0u;
    __syncthreads();
    if (tid < 128) {   // duplicated u rows: {b0,b0,b1,b1}
        int b = tid & 1, ju = tid >> 1;
        float v0 = u[(pb0 + 0 + b) * (TT * NIN) + ju];
        float v1 = u[(pb0 + 2 + b) * (TT * NIN) + ju];
        *reinterpret_cast<ull*>(&S->hx[0][0][NH + ju][2 * b]) = pack2(v0);
        *reinterpret_cast<ull*>(&S->hx[1][0][NH + ju][2 * b]) = pack2(v1);
    }
    __syncthreads();
    // flags + initial hx visible cluster-wide before any remote traffic
    asm volatile("barrier.cluster.arrive.aligned;" ::: "memory");
    asm volatile("barrier.cluster.wait.aligned;"   ::: "memory");

    // ---- per-thread precomputation ----
    // after the reduce: pair pp = lane bits {4,3}, batch bb = bit 2,
    // copy q = lane&3; lane owns full row i_loc and serves ranks 2q, 2q+1
    const int pp  = 2 * ((lane >> 4) & 1) + ((lane >> 3) & 1);
    const int bb  = (lane >> 2) & 1;
    const int q   = lane & 3;
    const int i_loc = w * 8 + 2 * pp + bb;
    const float bias_e = b_ih[r0 + w * 8 + 2 * pp]     + b_hh[r0 + w * 8 + 2 * pp];
    const float bias_o = b_ih[r0 + w * 8 + 2 * pp + 1] + b_hh[r0 + w * 8 + 2 * pp + 1];
    const float blr    = b_lin[(int)rank * 8 + w];
    const uint32_t rowbase = smem_u32(&S->hx[0][0][r0 + i_loc][0]);
    const uint32_t dst0 = mapa_u32(rowbase, (uint32_t)(2 * q));
    const uint32_t dst1 = mapa_u32(rowbase, (uint32_t)(2 * q + 1));
    // flag publish base (warp 0, lanes 0-7: one destination CTA each)
    uint32_t fdst = 0;
    if (w == 0 && lane < 8)
        fdst = mapa_u32(smem_u32(&S->flags[0][0][rank]), (uint32_t)lane);
    // local poll base: lane polls flags[...][lane&7]
    const uint32_t flbase = smem_u32(&S->flags[0][0][0]) + (uint32_t)((lane & 7) * 4);

    const int ub = tid & 1;      // u prefetch: batch (tid<128)
    const int ju = tid >> 1;     // u prefetch: input idx

    int bc = 0;                  // current buffer = kk % 3
    for (int kk = 0; kk < TOTIT; ++kk) {
        const int bn = (bc == NBUF - 1) ? 0 : bc + 1;
        const int t  = kk - FPIT;

        #pragma unroll
        for (int s = 0; s < 2; ++s) {
            // u prefetch for step kk+1 (issued before the wait; hidden)
            float u_next = 0.0f;
            if (tid < 128) {
                int tn = kk + 1 - FPIT;
                tn = (tn < 0) ? 0 : ((tn > TT - 1) ? (TT - 1) : tn);
                u_next = u[(pb0 + s * 2 + ub) * (TT * NIN) + tn * NIN + ju];
            }

            // wait for hx[s][bc] (skip step 0: locally initialized)
            if (kk > 0)
                flag_wait(flbase + FL_OFF(s, bc), (uint32_t)kk);

            const ulonglong2* hp2 =
                reinterpret_cast<const ulonglong2*>(&S->hx[s][bc][0][0]);

            // ---- matvec: 4 row-pairs x 2 batches, zero packing MOVs ----
            ull acc[4][2];
            #pragma unroll
            for (int p = 0; p < 4; ++p) { acc[p][0] = 0ull; acc[p][1] = 0ull; }
            #pragma unroll
            for (int k = 0; k < KPT; ++k) {
                ulonglong2 hv = hp2[lane + 32 * k];   // {b0,b0},{b1,b1}
                #pragma unroll
                for (int p = 0; p < 4; ++p) {
                    ffma2(acc[p][0], Apair[p][k], hv.x);
                    ffma2(acc[p][1], Apair[p][k], hv.y);
                }
            }

            // ---- distribute-reduce: lane ends with one full row-pair/batch
            ull e0[2], e1[2];
            {
                const bool sel = (lane & 16) != 0;
                #pragma unroll
                for (int b = 0; b < 2; ++b) {
                    ull sndA = sel ? acc[0][b] : acc[2][b];
                    ull rcvA = shfl64(sndA, 16);
                    e0[b] = addf2(sel ? acc[2][b] : acc[0][b], rcvA);
                    ull sndB = sel ? acc[1][b] : acc[3][b];
                    ull rcvB = shfl64(sndB, 16);
                    e1[b] = addf2(sel ? acc[3][b] : acc[1][b], rcvB);
                }
            }
            ull f[2];
            {
                const bool sel = (lane & 8) != 0;
                #pragma unroll
                for (int b = 0; b < 2; ++b) {
                    ull snd = sel ? e0[b] : e1[b];
                    ull rcv = shfl64(snd, 8);
                    f[b] = addf2(sel ? e1[b] : e0[b], rcv);
                }
            }
            ull dd;
            {
                const bool sel = (lane & 4) != 0;
                ull snd = sel ? f[0] : f[1];
                ull rcv = shfl64(snd, 4);
                dd = addf2(sel ? f[1] : f[0], rcv);
            }
            dd = addf2(dd, shfl64(dd, 2));
            dd = addf2(dd, shfl64(dd, 1));

            // ---- bias + tanh + batch transpose + DSMEM push ----
            {
                float s0, s1;
                unpack2(dd, s0, s1);
                const float he = tanh_fast(s0 + bias_e);  // even row, batch bb
                const float ho = tanh_fast(s1 + bias_o);  // odd row,  batch bb
                const float ge = __shfl_xor_sync(0xffffffffu, he, 4);
                const float go = __shfl_xor_sync(0xffffffffu, ho, 4);
                const float b0v = bb ? go : he;           // my row, batch 0
                const float b1v = bb ? ho : ge;           // my row, batch 1
                const ull lo = pack2(b0v);
                const ull hi = pack2(b1v);
                const uint32_t off = HX_OFF(s, bn);
                asm volatile("st.shared::cluster.v2.b64 [%0], {%1, %2};"
                             :: "r"(dst0 + off), "l"(lo), "l"(hi) : "memory");
                asm volatile("st.shared::cluster.v2.b64 [%0], {%1, %2};"
                             :: "r"(dst1 + off), "l"(lo), "l"(hi) : "memory");
            }
            // next step's input rows (local, duplicated layout)
            if (tid < 128)
                *reinterpret_cast<ull*>(&S->hx[s][bn][NH + ju][2 * ub]) =
                    pack2(u_next);

            // order all warps' stores, then publish flags (8 parallel release
            // stores to distinct addresses -- no atomic serialization)
            __syncthreads();
            if (w == 0 && lane < 8)
                FLAG_PUB(fdst + FL_OFF(s, bn), (uint32_t)(kk + 1));

            // head for step t-1 overlapped with the exchange window.
            // Safe with triple buffering: hx[s][bc] is only rewritten by
            // producers that acquired flag kk+2, which we publish only after
            // these reads complete (program order, next iteration).
            if (t >= 1)
                do_head(S, hp2, w, lane, pb0, s, (int)rank, blr, t - 1, out);
        }
        bc = bn;
    }

    // final heads: h_{TT-1} lives in hx[s][TOTIT%3]
    {
        const int bf = TOTIT % NBUF;
        #pragma unroll
        for (int s = 0; s < 2; ++s) {
            flag_wait(flbase + FL_OFF(s, bf), (uint32_t)TOTIT);
            const ulonglong2* hp2 =
                reinterpret_cast<const ulonglong2*>(&S->hx[s][bf][0][0]);
            do_head(S, hp2, w, lane, pb0, s, (int)rank, blr, TT - 1, out);
        }
    }
}

extern "C" void kernel_launch(void* const* d_in, const int* in_sizes, int n_in,
                              void* d_out, int out_size)
{
    const float* u     = (const float*)d_in[0];
    const float* W_ih  = (const float*)d_in[1];
    const float* W_hh  = (const float*)d_in[2];
    const float* b_ih  = (const float*)d_in[3];
    const float* b_hh  = (const float*)d_in[4];
    const float* omega = (const float*)d_in[5];
    const float* W_lin = (const float*)d_in[6];
    const float* b_lin = (const float*)d_in[7];
    float* out = (float*)d_out;

    cudaFuncSetAttribute(rnn_lyapunov_kernel,
                         cudaFuncAttributeMaxDynamicSharedMemorySize,
                         SMEM_BYTES);

    rnn_lyapunov_kernel<<<NCLUST * CSIZE, THREADS, SMEM_BYTES>>>(
        u, W_ih, W_hh, b_ih, b_hh, omega, W_lin, b_lin, out);
}

// round 15
// speedup vs baseline: 1.2933x; 1.2933x over previous
#include <cuda_runtime.h>
#include <cstdint>

// Problem constants
#define BB      64
#define TT      2048
#define NIN     64
#define NH      512
#define NOUT    64
#define FPIT    60
#define TOTIT   (FPIT + TT)

// Decomposition (R10 proven): 8 CTAs/cluster, 16 clusters,
// 2 streams x 2 batches per cluster, 256 threads, A in registers.
#define CSIZE   8
#define NCLUST  16
#define ROWS    64
#define THREADS 256
#define NWARP   8
#define JEXT    (NH + NIN)   // 576
#define KPT     18           // j's per lane: j = lane + 32k
#define NBUF    3            // triple buffer

typedef unsigned long long ull;

struct Smem {
    float hx[2][NBUF][JEXT][2];        // [stream][buf][j][batch]
    float Wl[8][NH];                   // this rank's 8 W_lin rows
    uint32_t flags[2][NBUF][8];        // [stream][buf][src_rank] = step counter
};
#define SMEM_BYTES  ((int)sizeof(Smem))
#define HXB_BYTES   (JEXT * 2 * 4)                        // 4608 per buffer
#define HX_OFF(s, b) ((uint32_t)(((s) * NBUF + (b)) * HXB_BYTES))
#define FL_OFF(s, b) ((uint32_t)(((s) * NBUF + (b)) * 32))

__device__ __forceinline__ uint32_t smem_u32(const void* p) {
    uint32_t a;
    asm("{ .reg .u64 t; cvta.to.shared.u64 t, %1; cvt.u32.u64 %0, t; }"
        : "=r"(a) : "l"(p));
    return a;
}
__device__ __forceinline__ uint32_t mapa_u32(uint32_t addr, uint32_t rank) {
    uint32_t r;
    asm("mapa.shared::cluster.u32 %0, %1, %2;" : "=r"(r) : "r"(addr), "r"(rank));
    return r;
}
__device__ __forceinline__ ull pack2(float a) {
    ull r;
    asm("mov.b64 %0, {%1, %1};" : "=l"(r) : "r"(__float_as_uint(a)));
    return r;
}
__device__ __forceinline__ ull packab(float a, float b) {
    ull r;
    asm("mov.b64 %0, {%1, %2};" : "=l"(r) : "r"(__float_as_uint(a)), "r"(__float_as_uint(b)));
    return r;
}
__device__ __forceinline__ void unpack2(ull v, float& a, float& b) {
    uint32_t x, y;
    asm("mov.b64 {%0, %1}, %2;" : "=r"(x), "=r"(y) : "l"(v));
    a = __uint_as_float(x); b = __uint_as_float(y);
}
__device__ __forceinline__ void ffma2(ull& acc, ull a, ull b) {
    asm("fma.rn.f32x2 %0, %1, %2, %0;" : "+l"(acc) : "l"(a), "l"(b));
}
__device__ __forceinline__ ull addf2(ull a, ull b) {
    ull r;
    asm("add.rn.f32x2 %0, %1, %2;" : "=l"(r) : "l"(a), "l"(b));
    return r;
}
__device__ __forceinline__ float tanh_fast(float x) {
    float r;
    asm("tanh.approx.f32 %0, %1;" : "=f"(r) : "f"(x));
    return r;
}

// flag publish: release store orders all our CTA's prior (bar.sync-ordered)
// DSMEM data stores before the flag becomes visible at cluster scope
#define FLAG_PUB(addr, val) \
    asm volatile("st.release.cluster.shared::cluster.u32 [%0], %1;" \
                 :: "r"(addr), "r"(val) : "memory")

// poll one flag word (this CTA's SMEM, written remotely) until >= need.
__device__ __forceinline__ void flag_wait(uint32_t addr, uint32_t need) {
    uint32_t v;
    do {
        asm volatile("ld.acquire.cluster.shared::cta.u32 %0, [%1];"
                     : "=r"(v) : "r"(addr) : "memory");
    } while (__any_sync(0xffffffffu, v < need));
}

// Head for stream s (2 batches): warp w owns output column rank*8 + w.
__device__ __forceinline__ void do_head(const Smem* S, const ull* hp, int w,
                                        int lane, int pb0, int s, int rank,
                                        float blr, int tt, float* __restrict__ out)
{
    ull acc = 0ull;
    const float* wl = &S->Wl[w][0];
    #pragma unroll
    for (int k = 0; k < 16; ++k) {
        int j = k * 32 + lane;
        ffma2(acc, pack2(wl[j]), hp[j]);
    }
    #pragma unroll
    for (int m = 16; m >= 1; m >>= 1)
        acc = addf2(acc, __shfl_xor_sync(0xffffffffu, acc, m));
    if (lane < 2) {
        float s0, s1;
        unpack2(acc, s0, s1);
        float v = lane ? s1 : s0;
        out[(pb0 + s * 2 + lane) * (TT * NOUT) + tt * NOUT + rank * 8 + w] = v + blr;
    }
}

extern __shared__ float smem_raw[];

__global__ void __cluster_dims__(CSIZE, 1, 1) __launch_bounds__(THREADS, 1)
rnn_lyapunov_kernel(const float* __restrict__ u,
                    const float* __restrict__ W_ih,
                    const float* __restrict__ W_hh,
                    const float* __restrict__ b_ih,
                    const float* __restrict__ b_hh,
                    const float* __restrict__ omega,
                    const float* __restrict__ W_lin,
                    const float* __restrict__ b_lin,
                    float* __restrict__ out)
{
    Smem* S = reinterpret_cast<Smem*>(smem_raw);
    const int tid  = threadIdx.x;
    const int w    = tid >> 5;
    const int lane = tid & 31;

    uint32_t rank;
    asm("mov.u32 %0, %%cluster_ctarank;" : "=r"(rank));
    const int cid = blockIdx.x >> 3;
    const int r0  = (int)rank * ROWS;
    const int pb0 = cid * 4;

    // ---- A into registers, row-pair packed: Apair[p][k] = {A[2p][j], A[2p+1][j]}
    ull Apair[4][KPT];
    {
        const int rg0 = r0 + w * 8;
        #pragma unroll
        for (int p = 0; p < 4; ++p) {
            const int re = rg0 + 2 * p;
            const int ro = re + 1;
            #pragma unroll
            for (int k = 0; k < 16; ++k) {
                int j = lane + 32 * k;
                float om = omega[j];
                float om2 = om * om;
                Apair[p][k] = packab(W_hh[re * NH + j] * om2,
                                     W_hh[ro * NH + j] * om2);
            }
            Apair[p][16] = packab(W_ih[re * NIN + lane],
                                  W_ih[ro * NIN + lane]);
            Apair[p][17] = packab(W_ih[re * NIN + 32 + lane],
                                  W_ih[ro * NIN + 32 + lane]);
        }
    }

    // ---- SMEM one-time loads ----
    for (int idx = tid; idx < 8 * NH; idx += THREADS) {
        int o = idx >> 9;
        int j = idx & (NH - 1);
        S->Wl[o][j] = W_lin[((int)rank * 8 + o) * NH + j];
    }
    // hx zero; flags zero
    for (int idx = tid; idx < 2 * NBUF * JEXT * 2; idx += THREADS)
        (&S->hx[0][0][0][0])[idx] = 0.0f;
    if (tid < 2 * NBUF * 8)
        (&S->flags[0][0][0])[tid] = 0u;
    __syncthreads();
    if (tid < 128) {
        int b = tid & 1, ju = tid >> 1;
        S->hx[0][0][NH + ju][b] = u[(pb0 + 0 + b) * (TT * NIN) + ju];
        S->hx[1][0][NH + ju][b] = u[(pb0 + 2 + b) * (TT * NIN) + ju];
    }
    __syncthreads();
    // flags + initial hx visible cluster-wide before any remote traffic
    asm volatile("barrier.cluster.arrive.aligned;" ::: "memory");
    asm volatile("barrier.cluster.wait.aligned;"   ::: "memory");

    // ---- per-thread precomputation ----
    // after the reduce, lane holds row rl = (lane>>2)&7; q = lane&3 serves
    // ranks 2q and 2q+1
    const int rl    = (lane >> 2) & 7;
    const int q     = lane & 3;
    const int i_loc = w * 8 + rl;
    const float bias_r = b_ih[r0 + i_loc] + b_hh[r0 + i_loc];
    const float blr    = b_lin[(int)rank * 8 + w];
    const uint32_t rowbase = smem_u32(&S->hx[0][0][r0 + i_loc][0]);
    const uint32_t dst0 = mapa_u32(rowbase, (uint32_t)(2 * q));
    const uint32_t dst1 = mapa_u32(rowbase, (uint32_t)(2 * q + 1));
    // flag publish base (warp 0, lanes 0-7: one destination CTA each)
    uint32_t fdst = 0;
    if (w == 0 && lane < 8)
        fdst = mapa_u32(smem_u32(&S->flags[0][0][rank]), (uint32_t)lane);
    // local poll base: lane polls flags[...][lane&7]
    const uint32_t flbase = smem_u32(&S->flags[0][0][0]) + (uint32_t)((lane & 7) * 4);

    const int ub = tid & 1;      // u prefetch: batch (tid<128)
    const int ju = tid >> 1;     // u prefetch: input idx

    int bc = 0;                  // current buffer = kk % 3
    for (int kk = 0; kk < TOTIT; ++kk) {
        const int bn = (bc == NBUF - 1) ? 0 : bc + 1;
        const int t  = kk - FPIT;

        #pragma unroll
        for (int s = 0; s < 2; ++s) {
            // u prefetch for step kk+1 (issued before the wait; hidden)
            float u_next = 0.0f;
            if (tid < 128) {
                int tn = kk + 1 - FPIT;
                tn = (tn < 0) ? 0 : ((tn > TT - 1) ? (TT - 1) : tn);
                u_next = u[(pb0 + s * 2 + ub) * (TT * NIN) + tn * NIN + ju];
            }

            // wait for hx[s][bc] (skip step 0: locally initialized)
            if (kk > 0)
                flag_wait(flbase + FL_OFF(s, bc), (uint32_t)kk);

            const ull* hp = reinterpret_cast<const ull*>(&S->hx[s][bc][0][0]);

            // ---- matvec: 4 row-pairs x 2 batches, 2 swap-MOVs per k
            // (replaces 8 per-use pack MOVs per k of the R10 version) ----
            ull accA[4] = {0ull, 0ull, 0ull, 0ull};
            ull accB[4] = {0ull, 0ull, 0ull, 0ull};
            #pragma unroll
            for (int k = 0; k < KPT; ++k) {
                ull hv = hp[lane + 32 * k];            // {b0, b1}
                uint32_t hx_, hy_;
                asm("mov.b64 {%0, %1}, %2;" : "=r"(hx_), "=r"(hy_) : "l"(hv));
                ull hs;
                asm("mov.b64 %0, {%1, %2};" : "=l"(hs) : "r"(hy_), "r"(hx_));
                #pragma unroll
                for (int p = 0; p < 4; ++p) {
                    ffma2(accA[p], Apair[p][k], hv);   // {A_e*b0, A_o*b1}
                    ffma2(accB[p], Apair[p][k], hs);   // {A_e*b1, A_o*b0}
                }
            }
            // repack once into R10's row-major d[8] = {b0, b1} per row
            ull d[8];
            #pragma unroll
            for (int p = 0; p < 4; ++p) {
                float aLo, aHi, bLo, bHi;
                unpack2(accA[p], aLo, aHi);
                unpack2(accB[p], bLo, bHi);
                d[2 * p]     = packab(aLo, bLo);       // row 2p:   {b0, b1}
                d[2 * p + 1] = packab(bHi, aHi);       // row 2p+1: {b0, b1}
            }

            // ---- distribute-reduce within the warp (identical to R10) ----
            {
                const bool sel = (lane & 16) != 0;
                #pragma unroll
                for (int i = 0; i < 4; ++i) {
                    ull snd = sel ? d[i] : d[i + 4];
                    ull rcv = __shfl_xor_sync(0xffffffffu, snd, 16);
                    d[i] = addf2(sel ? d[i + 4] : d[i], rcv);
                }
            }
            {
                const bool sel = (lane & 8) != 0;
                #pragma unroll
                for (int i = 0; i < 2; ++i) {
                    ull snd = sel ? d[i] : d[i + 2];
                    ull rcv = __shfl_xor_sync(0xffffffffu, snd, 8);
                    d[i] = addf2(sel ? d[i + 2] : d[i], rcv);
                }
            }
            ull dd;
            {
                const bool sel = (lane & 4) != 0;
                ull snd = sel ? d[0] : d[1];
                ull rcv = __shfl_xor_sync(0xffffffffu, snd, 4);
                dd = addf2(sel ? d[1] : d[0], rcv);
            }
            dd = addf2(dd, __shfl_xor_sync(0xffffffffu, dd, 2));
            dd = addf2(dd, __shfl_xor_sync(0xffffffffu, dd, 1));

            // ---- bias + tanh + DSMEM push (1 row -> 2 ranks) ----
            {
                float s0, s1;
                unpack2(dd, s0, s1);
                const float h0 = tanh_fast(s0 + bias_r);
                const float h1 = tanh_fast(s1 + bias_r);
                const ull pk = packab(h0, h1);
                const uint32_t off = HX_OFF(s, bn);
                asm volatile("st.shared::cluster.b64 [%0], %1;"
                             :: "r"(dst0 + off), "l"(pk) : "memory");
                asm volatile("st.shared::cluster.b64 [%0], %1;"
                             :: "r"(dst1 + off), "l"(pk) : "memory");
            }
            // next step's input rows (local)
            if (tid < 128)
                S->hx[s][bn][NH + ju][ub] = u_next;

            // order all warps' stores, then publish flags (8 parallel release
            // stores to distinct addresses -- no atomic serialization)
            __syncthreads();
            if (w == 0 && lane < 8)
                FLAG_PUB(fdst + FL_OFF(s, bn), (uint32_t)(kk + 1));

            // head for step t-1 overlapped with the exchange window.
            // Safe with triple buffering: hx[s][bc] is only rewritten by
            // producers that acquired flag kk+2, which we publish only after
            // these reads complete (program order, next iteration).
            if (t >= 1)
                do_head(S, hp, w, lane, pb0, s, (int)rank, blr, t - 1, out);
        }
        bc = bn;
    }

    // final heads: h_{TT-1} lives in hx[s][TOTIT%3]
    {
        const int bf = TOTIT % NBUF;
        #pragma unroll
        for (int s = 0; s < 2; ++s) {
            flag_wait(flbase + FL_OFF(s, bf), (uint32_t)TOTIT);
            const ull* hp = reinterpret_cast<const ull*>(&S->hx[s][bf][0][0]);
            do_head(S, hp, w, lane, pb0, s, (int)rank, blr, TT - 1, out);
        }
    }
}

extern "C" void kernel_launch(void* const* d_in, const int* in_sizes, int n_in,
                              void* d_out, int out_size)
{
    const float* u     = (const float*)d_in[0];
    const float* W_ih  = (const float*)d_in[1];
    const float* W_hh  = (const float*)d_in[2];
    const float* b_ih  = (const float*)d_in[3];
    const float* b_hh  = (const float*)d_in[4];
    const float* omega = (const float*)d_in[5];
    const float* W_lin = (const float*)d_in[6];
    const float* b_lin = (const float*)d_in[7];
    float* out = (float*)d_out;

    cudaFuncSetAttribute(rnn_lyapunov_kernel,
                         cudaFuncAttributeMaxDynamicSharedMemorySize,
                         SMEM_BYTES);

    rnn_lyapunov_kernel<<<NCLUST * CSIZE, THREADS, SMEM_BYTES>>>(
        u, W_ih, W_hh, b_ih, b_hh, omega, W_lin, b_lin, out);
}